// round 4
// baseline (speedup 1.0000x reference)
#include <cuda_runtime.h>
#include <math.h>

// ---------------------------------------------------------------------------
// SwinV2 block: B=32, H=W=48, C=384, NH=12, WS=12, SHIFT=6
// tokens M = 512 windows * 144 = 73728, head_dim=32, hidden=1536
// ---------------------------------------------------------------------------

#define M_TOK 73728
#define C_    384
#define NH_   12
#define N_    144
#define CH_   1536

// Scratch (device globals: allocation-free rule)
__device__ float g_qkv [84934656];   // 73728*1152
__device__ float g_attn[28311552];   // 73728*384
__device__ float g_proj[28311552];
__device__ float g_x1  [28311552];
__device__ float g_h1  [113246208];  // 73728*1536
__device__ float g_h2  [28311552];
__device__ float g_tab [529*12];
__device__ float g_bias[12*144*144];

// token index in window order -> row index in (b, h*48+w) order
// (roll(-6) + window partition for gather; identical map for scatter)
__device__ __forceinline__ int map_row(int m) {
    int w = m / 144, t = m - w * 144;
    int b = w >> 4, wi = (w >> 2) & 3, wj = w & 3;
    int ti = t / 12, tj = t - ti * 12;
    int sh = wi * 12 + ti + 6; if (sh >= 48) sh -= 48;
    int sw = wj * 12 + tj + 6; if (sw >= 48) sw -= 48;
    return b * 2304 + sh * 48 + sw;
}

// ---------------------------------------------------------------------------
// CPB MLP: tab[idx][h] = (relu(table[idx]@w1 + b1) @ w2)[h],   idx in [0,529)
// ---------------------------------------------------------------------------
__global__ void cpb_kernel(const float* __restrict__ table,
                           const float* __restrict__ w1,
                           const float* __restrict__ b1,
                           const float* __restrict__ w2) {
    int idx = blockIdx.x;
    int tid = threadIdx.x;
    __shared__ float hid[512];
    float t0 = table[idx * 2 + 0];
    float t1 = table[idx * 2 + 1];
    float h = t0 * w1[tid] + t1 * w1[512 + tid] + b1[tid];
    hid[tid] = fmaxf(h, 0.f);
    __syncthreads();
    if (tid < NH_) {
        float s = 0.f;
        for (int k = 0; k < 512; k++) s += hid[k] * w2[k * NH_ + tid];
        g_tab[idx * NH_ + tid] = s;
    }
}

// bias[h][i][j] = 16 * sigmoid(tab[rpi[i,j]][h])
__global__ void bias_kernel(const int* __restrict__ rpi) {
    int i = blockIdx.x, h = blockIdx.y, j = threadIdx.x;
    int idx = rpi[i * N_ + j];
    float v = g_tab[idx * NH_ + h];
    g_bias[(h * N_ + i) * N_ + j] = 16.f / (1.f + expf(-v));
}

// ---------------------------------------------------------------------------
// Tiled fp32 GEMM  (BM=BN=64, BK=16, 256 threads, 4x4 microtile)
// MODE 0: qkv  (A = x gathered via map_row, bias = [q_bias, 0, v_bias])
// MODE 1: proj (A = g_attn)                MODE 2: fc1+GELU (A = g_x1)
// MODE 3: fc2  (A = g_h1, K=1536)
// ---------------------------------------------------------------------------
template <int MODE>
__global__ void __launch_bounds__(256)
gemm_kernel(const float* __restrict__ Ain, const float* __restrict__ Bm,
            const float* __restrict__ bias, const float* __restrict__ bias2,
            int Ncols, int K) {
    __shared__ float As[16][68];
    __shared__ float Bs[16][64];
    const int tid = threadIdx.x;
    const int m0 = blockIdx.y * 64, n0 = blockIdx.x * 64;
    const int tx = tid & 15, ty = tid >> 4;

    const float* A;
    float* Cp;
    if (MODE == 0)      { A = Ain;    Cp = g_qkv;  }
    else if (MODE == 1) { A = g_attn; Cp = g_proj; }
    else if (MODE == 2) { A = g_x1;   Cp = g_h1;   }
    else                { A = g_h1;   Cp = g_h2;   }

    // rows this thread stages into smem: ty, ty+16, ty+32, ty+48
    const float* aptr[4];
#pragma unroll
    for (int it = 0; it < 4; it++) {
        int m = m0 + ty + it * 16;
        if (MODE == 0) aptr[it] = A + (long)map_row(m) * 384;
        else           aptr[it] = A + (long)m * K;
    }

    float acc[4][4];
#pragma unroll
    for (int i = 0; i < 4; i++)
#pragma unroll
        for (int j = 0; j < 4; j++) acc[i][j] = 0.f;

    const int rB = tid >> 6, cB = tid & 63;

    for (int k0 = 0; k0 < K; k0 += 16) {
#pragma unroll
        for (int it = 0; it < 4; it++)
            As[tx][ty + it * 16] = aptr[it][k0 + tx];
#pragma unroll
        for (int it = 0; it < 4; it++)
            Bs[rB + it * 4][cB] = Bm[(long)(k0 + rB + it * 4) * Ncols + n0 + cB];
        __syncthreads();
#pragma unroll
        for (int j = 0; j < 16; j++) {
            float4 av = *(const float4*)&As[j][ty * 4];
            float4 bv = *(const float4*)&Bs[j][tx * 4];
            acc[0][0] += av.x * bv.x; acc[0][1] += av.x * bv.y;
            acc[0][2] += av.x * bv.z; acc[0][3] += av.x * bv.w;
            acc[1][0] += av.y * bv.x; acc[1][1] += av.y * bv.y;
            acc[1][2] += av.y * bv.z; acc[1][3] += av.y * bv.w;
            acc[2][0] += av.z * bv.x; acc[2][1] += av.z * bv.y;
            acc[2][2] += av.z * bv.z; acc[2][3] += av.z * bv.w;
            acc[3][0] += av.w * bv.x; acc[3][1] += av.w * bv.y;
            acc[3][2] += av.w * bv.z; acc[3][3] += av.w * bv.w;
        }
        __syncthreads();
    }

#pragma unroll
    for (int i = 0; i < 4; i++) {
        int m = m0 + ty * 4 + i;
#pragma unroll
        for (int jj = 0; jj < 4; jj++) {
            int n = n0 + tx * 4 + jj;
            float v = acc[i][jj];
            if (MODE == 0) v += (n < 384) ? bias[n] : ((n < 768) ? 0.f : bias2[n - 768]);
            else           v += bias[n];
            if (MODE == 2) v = 0.5f * v * (1.f + erff(v * 0.70710678118654752f));
            Cp[(long)m * Ncols + n] = v;
        }
    }
}

// ---------------------------------------------------------------------------
// Cosine attention, one block per (window, head). 256 threads (8 warps).
// ---------------------------------------------------------------------------
__global__ void __launch_bounds__(256)
attn_kernel(const float* __restrict__ mask, const float* __restrict__ logit_scale) {
    const int w = blockIdx.x, h = blockIdx.y;
    const int tid = threadIdx.x, warp = tid >> 5, lane = tid & 31;

    __shared__ float ks[144 * 33];
    __shared__ float vs[144 * 33];
    __shared__ float kinv[144];
    __shared__ float srow[8][144];
    __shared__ float qrow[8][32];

    const float* base = g_qkv + (long)w * 144 * 1152 + h * 32;

    for (int idx = tid; idx < 144 * 32; idx += 256) {
        int t = idx >> 5, d = idx & 31;
        ks[t * 33 + d] = base[t * 1152 + 384 + d];
        vs[t * 33 + d] = base[t * 1152 + 768 + d];
    }
    __syncthreads();
    if (tid < 144) {
        float s = 0.f;
#pragma unroll
        for (int d = 0; d < 32; d++) { float kv = ks[tid * 33 + d]; s += kv * kv; }
        kinv[tid] = 1.f / fmaxf(sqrtf(s), 1e-12f);
    }
    const float scale = expf(fminf(logit_scale[h], 4.6051701859880914f));  // ln(100)
    const float* mrow = mask + (long)(w & 15) * N_ * N_;
    const float* brow = g_bias + (long)h * N_ * N_;
    __syncthreads();

    for (int r = warp; r < 144; r += 8) {
        qrow[warp][lane] = base[r * 1152 + lane];
        __syncwarp();
        float qv = qrow[warp][lane];
        float ss = qv * qv;
#pragma unroll
        for (int o = 16; o; o >>= 1) ss += __shfl_xor_sync(0xffffffffu, ss, o);
        float qinv = 1.f / fmaxf(sqrtf(ss), 1e-12f);

        float sloc[5];
        float mx = -1e30f;
#pragma unroll
        for (int jj = 0; jj < 5; jj++) {
            int j = lane + jj * 32;
            sloc[jj] = -1e30f;
            if (j < 144) {
                float dot = 0.f;
#pragma unroll
                for (int d = 0; d < 32; d++) dot += qrow[warp][d] * ks[j * 33 + d];
                float s = dot * qinv * kinv[j] * scale
                        + brow[r * N_ + j] + mrow[r * N_ + j];
                sloc[jj] = s;
                mx = fmaxf(mx, s);
            }
        }
#pragma unroll
        for (int o = 16; o; o >>= 1) mx = fmaxf(mx, __shfl_xor_sync(0xffffffffu, mx, o));
        float sum = 0.f;
#pragma unroll
        for (int jj = 0; jj < 5; jj++) {
            int j = lane + jj * 32;
            if (j < 144) {
                float p = expf(sloc[jj] - mx);
                srow[warp][j] = p;
                sum += p;
            }
        }
#pragma unroll
        for (int o = 16; o; o >>= 1) sum += __shfl_xor_sync(0xffffffffu, sum, o);
        float invs = 1.f / sum;
        __syncwarp();

        float accd = 0.f;
        for (int j = 0; j < 144; j++) accd += srow[warp][j] * vs[j * 33 + lane];
        g_attn[((long)w * 144 + r) * 384 + h * 32 + lane] = accd * invs;
        __syncwarp();
    }
}

// ---------------------------------------------------------------------------
// Scatter + LayerNorm1 + residual:  x1[dst] = x0[dst] + LN(proj_out[m])
// ---------------------------------------------------------------------------
__global__ void __launch_bounds__(384)
ln1_kernel(const float* __restrict__ x0, const float* __restrict__ g,
           const float* __restrict__ b) {
    int m = blockIdx.x, c = threadIdx.x;
    float v = g_proj[(long)m * C_ + c];
    float s1 = v, s2 = v * v;
#pragma unroll
    for (int o = 16; o; o >>= 1) {
        s1 += __shfl_xor_sync(0xffffffffu, s1, o);
        s2 += __shfl_xor_sync(0xffffffffu, s2, o);
    }
    __shared__ float a1[12], a2[12];
    int wid = c >> 5;
    if ((c & 31) == 0) { a1[wid] = s1; a2[wid] = s2; }
    __syncthreads();
    if (c == 0) {
        float t1 = 0.f, t2 = 0.f;
        for (int i = 0; i < 12; i++) { t1 += a1[i]; t2 += a2[i]; }
        a1[0] = t1; a2[0] = t2;
    }
    __syncthreads();
    float mean = a1[0] * (1.f / 384.f);
    float var  = a2[0] * (1.f / 384.f) - mean * mean;
    float inv  = rsqrtf(var + 1e-5f);
    long dst = (long)map_row(m) * C_;
    g_x1[dst + c] = x0[dst + c] + (v - mean) * inv * g[c] + b[c];
}

// LayerNorm2 + residual:  out[m] = x1[m] + LN(h2[m])
__global__ void __launch_bounds__(384)
ln2_kernel(const float* __restrict__ g, const float* __restrict__ b,
           float* __restrict__ out) {
    int m = blockIdx.x, c = threadIdx.x;
    float v = g_h2[(long)m * C_ + c];
    float s1 = v, s2 = v * v;
#pragma unroll
    for (int o = 16; o; o >>= 1) {
        s1 += __shfl_xor_sync(0xffffffffu, s1, o);
        s2 += __shfl_xor_sync(0xffffffffu, s2, o);
    }
    __shared__ float a1[12], a2[12];
    int wid = c >> 5;
    if ((c & 31) == 0) { a1[wid] = s1; a2[wid] = s2; }
    __syncthreads();
    if (c == 0) {
        float t1 = 0.f, t2 = 0.f;
        for (int i = 0; i < 12; i++) { t1 += a1[i]; t2 += a2[i]; }
        a1[0] = t1; a2[0] = t2;
    }
    __syncthreads();
    float mean = a1[0] * (1.f / 384.f);
    float var  = a2[0] * (1.f / 384.f) - mean * mean;
    float inv  = rsqrtf(var + 1e-5f);
    long idx = (long)m * C_ + c;
    out[idx] = g_x1[idx] + (v - mean) * inv * g[c] + b[c];
}

// ---------------------------------------------------------------------------
extern "C" void kernel_launch(void* const* d_in, const int* in_sizes, int n_in,
                              void* d_out, int out_size) {
    (void)in_sizes; (void)n_in; (void)out_size;
    const float* x       = (const float*)d_in[0];
    const float* table   = (const float*)d_in[1];
    const int*   rpi     = (const int*)  d_in[2];
    const float* mask    = (const float*)d_in[3];
    const float* qkv_w   = (const float*)d_in[4];
    const float* q_bias  = (const float*)d_in[5];
    const float* v_bias  = (const float*)d_in[6];
    const float* lscale  = (const float*)d_in[7];
    const float* cpb_w1  = (const float*)d_in[8];
    const float* cpb_b1  = (const float*)d_in[9];
    const float* cpb_w2  = (const float*)d_in[10];
    const float* proj_w  = (const float*)d_in[11];
    const float* proj_b  = (const float*)d_in[12];
    const float* n1g     = (const float*)d_in[13];
    const float* n1b     = (const float*)d_in[14];
    const float* n2g     = (const float*)d_in[15];
    const float* n2b     = (const float*)d_in[16];
    const float* fc1_w   = (const float*)d_in[17];
    const float* fc1_b   = (const float*)d_in[18];
    const float* fc2_w   = (const float*)d_in[19];
    const float* fc2_b   = (const float*)d_in[20];
    float* out = (float*)d_out;

    // 1. continuous position bias
    cpb_kernel<<<529, 512>>>(table, cpb_w1, cpb_b1, cpb_w2);
    bias_kernel<<<dim3(144, 12), 144>>>(rpi);

    // 2. QKV projection (gathered A)
    gemm_kernel<0><<<dim3(1152 / 64, M_TOK / 64), 256>>>(x, qkv_w, q_bias, v_bias, 1152, 384);

    // 3. cosine attention
    attn_kernel<<<dim3(512, 12), 256>>>(mask, lscale);

    // 4. output projection, then scatter + LN1 + residual
    gemm_kernel<1><<<dim3(384 / 64, M_TOK / 64), 256>>>(nullptr, proj_w, proj_b, nullptr, 384, 384);
    ln1_kernel<<<M_TOK, 384>>>(x, n1g, n1b);

    // 5. MLP
    gemm_kernel<2><<<dim3(1536 / 64, M_TOK / 64), 256>>>(nullptr, fc1_w, fc1_b, nullptr, 1536, 384);
    gemm_kernel<3><<<dim3(384 / 64, M_TOK / 64), 256>>>(nullptr, fc2_w, fc2_b, nullptr, 384, 1536);

    // 6. LN2 + residual -> output
    ln2_kernel<<<M_TOK, 384>>>(n2g, n2b, out);
}

// round 9
// speedup vs baseline: 1.5187x; 1.5187x over previous
#include <cuda_runtime.h>
#include <cuda_bf16.h>
#include <math.h>
#include <stdint.h>

// ---------------------------------------------------------------------------
// SwinV2 block: B=32, H=W=48, C=384, NH=12, WS=12, SHIFT=6
// tokens M = 512 windows * 144 = 73728, head_dim=32, hidden=1536
// GEMMs on tensor cores: mma.sync m16n8k16 bf16, 3-term split for fp32-ish acc
// ---------------------------------------------------------------------------

#define M_TOK 73728
#define C_    384
#define NH_   12
#define N_    144
#define CH_   1536

// Scratch (device globals: allocation-free rule)
__device__ float g_qkv [84934656];   // 73728*1152
__device__ float g_attn[28311552];   // 73728*384
__device__ float g_proj[28311552];
__device__ float g_x1  [28311552];
__device__ float g_h1  [113246208];  // 73728*1536
__device__ float g_h2  [28311552];
__device__ float g_tab [529*12];
__device__ float g_bias[12*144*144];

// token index in window order -> row index in (b, h*48+w) order
__device__ __forceinline__ int map_row(int m) {
    int w = m / 144, t = m - w * 144;
    int b = w >> 4, wi = (w >> 2) & 3, wj = w & 3;
    int ti = t / 12, tj = t - ti * 12;
    int sh = wi * 12 + ti + 6; if (sh >= 48) sh -= 48;
    int sw = wj * 12 + tj + 6; if (sw >= 48) sw -= 48;
    return b * 2304 + sh * 48 + sw;
}

// ---------------------------------------------------------------------------
// CPB MLP + bias table
// ---------------------------------------------------------------------------
__global__ void cpb_kernel(const float* __restrict__ table,
                           const float* __restrict__ w1,
                           const float* __restrict__ b1,
                           const float* __restrict__ w2) {
    int idx = blockIdx.x;
    int tid = threadIdx.x;
    __shared__ float hid[512];
    float t0 = table[idx * 2 + 0];
    float t1 = table[idx * 2 + 1];
    float h = t0 * w1[tid] + t1 * w1[512 + tid] + b1[tid];
    hid[tid] = fmaxf(h, 0.f);
    __syncthreads();
    if (tid < NH_) {
        float s = 0.f;
        for (int k = 0; k < 512; k++) s += hid[k] * w2[k * NH_ + tid];
        g_tab[idx * NH_ + tid] = s;
    }
}

__global__ void bias_kernel(const int* __restrict__ rpi) {
    int i = blockIdx.x, h = blockIdx.y, j = threadIdx.x;
    int idx = rpi[i * N_ + j];
    float v = g_tab[idx * NH_ + h];
    g_bias[(h * N_ + i) * N_ + j] = 16.f / (1.f + expf(-v));
}

// ---------------------------------------------------------------------------
// Tensor-core GEMM: 3xBF16 split.  Block tile 128x64, 8 warps (4x2),
// warp tile 32x32, K-step 16.
// MODE 0: qkv  (A gathered via map_row; bias [q_bias,0,v_bias])
// MODE 1: proj   MODE 2: fc1+GELU   MODE 3: fc2 (K=1536)
// ---------------------------------------------------------------------------
__device__ __forceinline__ void mma16816(float* c, const uint32_t* a,
                                         const uint32_t* b) {
    asm volatile(
        "mma.sync.aligned.m16n8k16.row.col.f32.bf16.bf16.f32 "
        "{%0,%1,%2,%3}, {%4,%5,%6,%7}, {%8,%9}, {%0,%1,%2,%3};\n"
        : "+f"(c[0]), "+f"(c[1]), "+f"(c[2]), "+f"(c[3])
        : "r"(a[0]), "r"(a[1]), "r"(a[2]), "r"(a[3]), "r"(b[0]), "r"(b[1]));
}

template <int MODE>
__global__ void __launch_bounds__(256)
gemm_tc(const float* __restrict__ Ain, const float* __restrict__ Bm,
        const float* __restrict__ bias, const float* __restrict__ bias2,
        int Ncols, int K) {
    // A: [128 rows][8 k-pairs] packed bf16x2, hi & lo planes (pad 9)
    __shared__ uint32_t AsH[128][9];
    __shared__ uint32_t AsL[128][9];
    // B: [64 cols][16 k] bf16 (pad 20 -> 10 uint32 pairs)
    __shared__ uint32_t BsH[64][10];
    __shared__ uint32_t BsL[64][10];

    const int tid  = threadIdx.x;
    const int lane = tid & 31, warp = tid >> 5;
    const int warpM = warp >> 1, warpN = warp & 1;
    const int g = lane >> 2, tig = lane & 3;
    const int m0 = blockIdx.y * 128, n0 = blockIdx.x * 64;

    const float* A;
    float* Cp;
    if (MODE == 0)      { A = Ain;    Cp = g_qkv;  }
    else if (MODE == 1) { A = g_attn; Cp = g_proj; }
    else if (MODE == 2) { A = g_x1;   Cp = g_h1;   }
    else                { A = g_h1;   Cp = g_h2;   }

    // A staging map: thread -> rows (tid>>3)+32i, k-pair (tid&7)
    const int arow = tid >> 3;
    const int akp  = tid & 7;
    const float* aptr[4];
#pragma unroll
    for (int i = 0; i < 4; i++) {
        int m = m0 + arow + 32 * i;
        aptr[i] = (MODE == 0) ? A + (long)map_row(m) * 384 : A + (long)m * K;
    }
    // B staging map: thread -> col (tid&63), k (tid>>6)+4i
    const int bn  = tid & 63;
    const int bk0 = tid >> 6;
    __nv_bfloat16* BsHb = (__nv_bfloat16*)BsH;
    __nv_bfloat16* BsLb = (__nv_bfloat16*)BsL;

    float acc[2][4][4];
#pragma unroll
    for (int mt = 0; mt < 2; mt++)
#pragma unroll
        for (int nt = 0; nt < 4; nt++)
#pragma unroll
            for (int i = 0; i < 4; i++) acc[mt][nt][i] = 0.f;

    for (int k0 = 0; k0 < K; k0 += 16) {
        // ---- stage A (float2 -> bf16 hi/lo pair) ----
#pragma unroll
        for (int i = 0; i < 4; i++) {
            float2 v = *(const float2*)(aptr[i] + k0 + 2 * akp);
            __nv_bfloat162 hi = __floats2bfloat162_rn(v.x, v.y);
            float r0 = v.x - __low2float(hi);
            float r1 = v.y - __high2float(hi);
            __nv_bfloat162 lo = __floats2bfloat162_rn(r0, r1);
            AsH[arow + 32 * i][akp] = *(uint32_t*)&hi;
            AsL[arow + 32 * i][akp] = *(uint32_t*)&lo;
        }
        // ---- stage B ----
#pragma unroll
        for (int i = 0; i < 4; i++) {
            int k = bk0 + 4 * i;
            float v = Bm[(long)(k0 + k) * Ncols + n0 + bn];
            __nv_bfloat16 hb = __float2bfloat16(v);
            __nv_bfloat16 lb = __float2bfloat16(v - __bfloat162float(hb));
            BsHb[bn * 20 + k] = hb;
            BsLb[bn * 20 + k] = lb;
        }
        __syncthreads();

        // ---- fragments ----
        uint32_t aH[2][4], aL[2][4];
#pragma unroll
        for (int mt = 0; mt < 2; mt++) {
            int r = warpM * 32 + mt * 16 + g;
            aH[mt][0] = AsH[r][tig];     aH[mt][1] = AsH[r + 8][tig];
            aH[mt][2] = AsH[r][tig + 4]; aH[mt][3] = AsH[r + 8][tig + 4];
            aL[mt][0] = AsL[r][tig];     aL[mt][1] = AsL[r + 8][tig];
            aL[mt][2] = AsL[r][tig + 4]; aL[mt][3] = AsL[r + 8][tig + 4];
        }
        uint32_t bH[4][2], bL[4][2];
#pragma unroll
        for (int nt = 0; nt < 4; nt++) {
            int n = warpN * 32 + nt * 8 + g;
            bH[nt][0] = BsH[n][tig]; bH[nt][1] = BsH[n][tig + 4];
            bL[nt][0] = BsL[n][tig]; bL[nt][1] = BsL[n][tig + 4];
        }
#pragma unroll
        for (int mt = 0; mt < 2; mt++)
#pragma unroll
            for (int nt = 0; nt < 4; nt++) {
                mma16816(acc[mt][nt], aH[mt], bH[nt]);
                mma16816(acc[mt][nt], aL[mt], bH[nt]);
                mma16816(acc[mt][nt], aH[mt], bL[nt]);
            }
        __syncthreads();
    }

    // ---- epilogue ----
#pragma unroll
    for (int mt = 0; mt < 2; mt++) {
#pragma unroll
        for (int nt = 0; nt < 4; nt++) {
            int row = m0 + warpM * 32 + mt * 16 + g;
            int col = n0 + warpN * 32 + nt * 8 + tig * 2;
#pragma unroll
            for (int i = 0; i < 4; i++) {
                int m = row + (i >> 1) * 8;
                int n = col + (i & 1);
                float v = acc[mt][nt][(i >> 1) * 2 + (i & 1)];
                if (MODE == 0) v += (n < 384) ? bias[n] : ((n < 768) ? 0.f : bias2[n - 768]);
                else           v += bias[n];
                if (MODE == 2) v = 0.5f * v * (1.f + erff(v * 0.70710678118654752f));
                Cp[(long)m * Ncols + n] = v;
            }
        }
    }
}

// ---------------------------------------------------------------------------
// Cosine attention, one block per (window, head). 256 threads (8 warps).
// ---------------------------------------------------------------------------
__global__ void __launch_bounds__(256)
attn_kernel(const float* __restrict__ mask, const float* __restrict__ logit_scale) {
    const int w = blockIdx.x, h = blockIdx.y;
    const int tid = threadIdx.x, warp = tid >> 5, lane = tid & 31;

    __shared__ float ks[144 * 33];
    __shared__ float vs[144 * 33];
    __shared__ float kinv[144];
    __shared__ float srow[8][144];
    __shared__ float qrow[8][32];

    const float* base = g_qkv + (long)w * 144 * 1152 + h * 32;

    for (int idx = tid; idx < 144 * 32; idx += 256) {
        int t = idx >> 5, d = idx & 31;
        ks[t * 33 + d] = base[t * 1152 + 384 + d];
        vs[t * 33 + d] = base[t * 1152 + 768 + d];
    }
    __syncthreads();
    if (tid < 144) {
        float s = 0.f;
#pragma unroll
        for (int d = 0; d < 32; d++) { float kv = ks[tid * 33 + d]; s += kv * kv; }
        kinv[tid] = 1.f / fmaxf(sqrtf(s), 1e-12f);
    }
    const float scale = expf(fminf(logit_scale[h], 4.6051701859880914f));  // ln(100)
    const float* mrow = mask + (long)(w & 15) * N_ * N_;
    const float* brow = g_bias + (long)h * N_ * N_;
    __syncthreads();

    for (int r = warp; r < 144; r += 8) {
        qrow[warp][lane] = base[r * 1152 + lane];
        __syncwarp();
        float qv = qrow[warp][lane];
        float ss = qv * qv;
#pragma unroll
        for (int o = 16; o; o >>= 1) ss += __shfl_xor_sync(0xffffffffu, ss, o);
        float qinv = 1.f / fmaxf(sqrtf(ss), 1e-12f);

        float sloc[5];
        float mx = -1e30f;
#pragma unroll
        for (int jj = 0; jj < 5; jj++) {
            int j = lane + jj * 32;
            sloc[jj] = -1e30f;
            if (j < 144) {
                float dot = 0.f;
#pragma unroll
                for (int d = 0; d < 32; d++) dot += qrow[warp][d] * ks[j * 33 + d];
                float s = dot * qinv * kinv[j] * scale
                        + brow[r * N_ + j] + mrow[r * N_ + j];
                sloc[jj] = s;
                mx = fmaxf(mx, s);
            }
        }
#pragma unroll
        for (int o = 16; o; o >>= 1) mx = fmaxf(mx, __shfl_xor_sync(0xffffffffu, mx, o));
        float sum = 0.f;
#pragma unroll
        for (int jj = 0; jj < 5; jj++) {
            int j = lane + jj * 32;
            if (j < 144) {
                float p = expf(sloc[jj] - mx);
                srow[warp][j] = p;
                sum += p;
            }
        }
#pragma unroll
        for (int o = 16; o; o >>= 1) sum += __shfl_xor_sync(0xffffffffu, sum, o);
        float invs = 1.f / sum;
        __syncwarp();

        float accd = 0.f;
        for (int j = 0; j < 144; j++) accd += srow[warp][j] * vs[j * 33 + lane];
        g_attn[((long)w * 144 + r) * 384 + h * 32 + lane] = accd * invs;
        __syncwarp();
    }
}

// ---------------------------------------------------------------------------
// Scatter + LayerNorm1 + residual
// ---------------------------------------------------------------------------
__global__ void __launch_bounds__(384)
ln1_kernel(const float* __restrict__ x0, const float* __restrict__ g,
           const float* __restrict__ b) {
    int m = blockIdx.x, c = threadIdx.x;
    float v = g_proj[(long)m * C_ + c];
    float s1 = v, s2 = v * v;
#pragma unroll
    for (int o = 16; o; o >>= 1) {
        s1 += __shfl_xor_sync(0xffffffffu, s1, o);
        s2 += __shfl_xor_sync(0xffffffffu, s2, o);
    }
    __shared__ float a1[12], a2[12];
    int wid = c >> 5;
    if ((c & 31) == 0) { a1[wid] = s1; a2[wid] = s2; }
    __syncthreads();
    if (c == 0) {
        float t1 = 0.f, t2 = 0.f;
        for (int i = 0; i < 12; i++) { t1 += a1[i]; t2 += a2[i]; }
        a1[0] = t1; a2[0] = t2;
    }
    __syncthreads();
    float mean = a1[0] * (1.f / 384.f);
    float var  = a2[0] * (1.f / 384.f) - mean * mean;
    float inv  = rsqrtf(var + 1e-5f);
    long dst = (long)map_row(m) * C_;
    g_x1[dst + c] = x0[dst + c] + (v - mean) * inv * g[c] + b[c];
}

__global__ void __launch_bounds__(384)
ln2_kernel(const float* __restrict__ g, const float* __restrict__ b,
           float* __restrict__ out) {
    int m = blockIdx.x, c = threadIdx.x;
    float v = g_h2[(long)m * C_ + c];
    float s1 = v, s2 = v * v;
#pragma unroll
    for (int o = 16; o; o >>= 1) {
        s1 += __shfl_xor_sync(0xffffffffu, s1, o);
        s2 += __shfl_xor_sync(0xffffffffu, s2, o);
    }
    __shared__ float a1[12], a2[12];
    int wid = c >> 5;
    if ((c & 31) == 0) { a1[wid] = s1; a2[wid] = s2; }
    __syncthreads();
    if (c == 0) {
        float t1 = 0.f, t2 = 0.f;
        for (int i = 0; i < 12; i++) { t1 += a1[i]; t2 += a2[i]; }
        a1[0] = t1; a2[0] = t2;
    }
    __syncthreads();
    float mean = a1[0] * (1.f / 384.f);
    float var  = a2[0] * (1.f / 384.f) - mean * mean;
    float inv  = rsqrtf(var + 1e-5f);
    long idx = (long)m * C_ + c;
    out[idx] = g_x1[idx] + (v - mean) * inv * g[c] + b[c];
}

// ---------------------------------------------------------------------------
extern "C" void kernel_launch(void* const* d_in, const int* in_sizes, int n_in,
                              void* d_out, int out_size) {
    (void)in_sizes; (void)n_in; (void)out_size;
    const float* x       = (const float*)d_in[0];
    const float* table   = (const float*)d_in[1];
    const int*   rpi     = (const int*)  d_in[2];
    const float* mask    = (const float*)d_in[3];
    const float* qkv_w   = (const float*)d_in[4];
    const float* q_bias  = (const float*)d_in[5];
    const float* v_bias  = (const float*)d_in[6];
    const float* lscale  = (const float*)d_in[7];
    const float* cpb_w1  = (const float*)d_in[8];
    const float* cpb_b1  = (const float*)d_in[9];
    const float* cpb_w2  = (const float*)d_in[10];
    const float* proj_w  = (const float*)d_in[11];
    const float* proj_b  = (const float*)d_in[12];
    const float* n1g     = (const float*)d_in[13];
    const float* n1b     = (const float*)d_in[14];
    const float* n2g     = (const float*)d_in[15];
    const float* n2b     = (const float*)d_in[16];
    const float* fc1_w   = (const float*)d_in[17];
    const float* fc1_b   = (const float*)d_in[18];
    const float* fc2_w   = (const float*)d_in[19];
    const float* fc2_b   = (const float*)d_in[20];
    float* out = (float*)d_out;

    cpb_kernel<<<529, 512>>>(table, cpb_w1, cpb_b1, cpb_w2);
    bias_kernel<<<dim3(144, 12), 144>>>(rpi);

    gemm_tc<0><<<dim3(1152 / 64, M_TOK / 128), 256>>>(x, qkv_w, q_bias, v_bias, 1152, 384);

    attn_kernel<<<dim3(512, 12), 256>>>(mask, lscale);

    gemm_tc<1><<<dim3(384 / 64, M_TOK / 128), 256>>>(nullptr, proj_w, proj_b, nullptr, 384, 384);
    ln1_kernel<<<M_TOK, 384>>>(x, n1g, n1b);

    gemm_tc<2><<<dim3(1536 / 64, M_TOK / 128), 256>>>(nullptr, fc1_w, fc1_b, nullptr, 1536, 384);
    gemm_tc<3><<<dim3(384 / 64, M_TOK / 128), 256>>>(nullptr, fc2_w, fc2_b, nullptr, 384, 1536);

    ln2_kernel<<<M_TOK, 384>>>(n2g, n2b, out);
}